// round 15
// baseline (speedup 1.0000x reference)
#include <cuda_runtime.h>
#include <stdint.h>

// AE_spikes: ONE fused kernel, 8 batch rows/CTA, enc->L1->..->L4 in smem.
// s8 mma.sync, 2 weight limbs base 254, exact int32 accumulation, fused
// fire-and-reset scan, in-CTA flag + bit-exact fp32 repair.
// R13 (resubmit after infra failure): XOR-swizzled B (pitch 128,
// conflict-free), true double-buffered B for K=128 layers (2-deep cp.async
// pipeline), paired scan chains (LDS.64), K128 scan buffer overlaid on dead
// M0. Same 75792B smem -> 3 CTAs/SM.

#define BATCH  16384
#define TSTEPS 16
#define KP1    896
#define EPS    1e-3f
#define FCAPS  512

// smem layout (bytes)
#define OFF_M0 0        // L1 masks 8x896 u16 PERMUTED (14336); K128 cs overlays
#define OFF_BB 34816    // B bufs: 2 x 16384 -> ends 67584; L1 cs overlays (34816B)
#define OFF_M1 69632    // 8 x 128 u16 PERMUTED (2048)
#define OFF_M2 71680    // (2048)
#define OFF_FC 73728    // flag counter (16)
#define OFF_FL 73744    // flag list u32 x 512 (2048)
#define SMEMSZ 75792

// logical neuron index -> permuted u16 slot (pairs (0,2),(1,3) per u64)
#define PERM4(i) (((i) & ~3) | ((((i) & 1) << 1) | (((i) >> 1) & 1)))

// ---------------- weight scratch ----------------
__device__ int8_t g_Q1[2 * 128 * KP1];
__device__ int8_t g_Q2[2 * 128 * 128];
__device__ int8_t g_Q3[2 * 128 * 128];
__device__ int8_t g_Q4[2 * 784 * 128];
__device__ float  g_S1[128], g_S2[128], g_S3[128], g_S4[784];

// ---------------- helpers ----------------
__device__ __forceinline__ uint32_t smem_u32(const void* p) {
    uint32_t a;
    asm("{ .reg .u64 t; cvta.to.shared.u64 t, %1; cvt.u32.u64 %0, t; }"
        : "=r"(a) : "l"(p));
    return a;
}
__device__ __forceinline__ void mma8(int* d, const uint32_t* a, uint32_t b0, uint32_t b1) {
    asm volatile(
        "mma.sync.aligned.m16n8k32.row.col.s32.s8.s8.s32 "
        "{%0,%1,%2,%3}, {%4,%5,%6,%7}, {%8,%9}, {%0,%1,%2,%3};"
        : "+r"(d[0]), "+r"(d[1]), "+r"(d[2]), "+r"(d[3])
        : "r"(a[0]), "r"(a[1]), "r"(a[2]), "r"(a[3]), "r"(b0), "r"(b1));
}
__device__ __forceinline__ void cpa16(uint32_t dst, const void* src, uint32_t ssz) {
    asm volatile("cp.async.cg.shared.global [%0], [%1], 16, %2;"
                 :: "r"(dst), "l"(src), "r"(ssz));
}

// ---------------- weight split (one launch) ----------------
__device__ void wsplit_one(const float* W, int8_t* Q, float* S,
                           int N, int K, int KP, int j, int lane) {
    const float* w = W + (size_t)j * K;
    float m = 0.0f;
    for (int k = lane; k < K; k += 32) m = fmaxf(m, fabsf(w[k]));
#pragma unroll
    for (int o = 16; o; o >>= 1) m = fmaxf(m, __shfl_xor_sync(~0u, m, o));
    float s0 = (m > 0.0f) ? m / 127.0f : 1.0f;
    if (lane == 0) S[j] = s0;
    double s0d = (double)s0;
    for (int k = lane; k < KP; k += 32) {
        double q0 = 0.0, q1 = 0.0;
        if (k < K) {
            double wd = (double)w[k];
            q0 = fmin(fmax(rint(wd / s0d), -127.0), 127.0);
            double r1 = wd - q0 * s0d;
            q1 = fmin(fmax(rint(r1 * 254.0 / s0d), -127.0), 127.0);
        }
        size_t base = (size_t)j * KP + k, lstr = (size_t)N * KP;
        Q[base]        = (int8_t)(int)q0;
        Q[base + lstr] = (int8_t)(int)q1;
    }
}
__global__ void __launch_bounds__(32) wsplit_all(
    const float* __restrict__ W1, const float* __restrict__ W2,
    const float* __restrict__ W3, const float* __restrict__ W4)
{
    int bid = blockIdx.x, lane = threadIdx.x;
    if      (bid < 128) wsplit_one(W1, g_Q1, g_S1, 128, 784, KP1, bid, lane);
    else if (bid < 256) wsplit_one(W2, g_Q2, g_S2, 128, 128, 128, bid - 128, lane);
    else if (bid < 384) wsplit_one(W3, g_Q3, g_S3, 128, 128, 128, bid - 256, lane);
    else                wsplit_one(W4, g_Q4, g_S4, 784, 128, 128, bid - 384, lane);
}

// ---------------- register A-expansion + MMA over one K=128 panel ---------
// Masks permuted per u64: lo=(m0|m2<<16), hi=(m1|m3<<16).
// B stored swizzled: row r pitch 128, 16B chunk c stored at (c ^ (r&7)).
__device__ __forceinline__ void mma_panel_reg(
    const char* sm, int msk_off, int kpu64, int p, const char* bbase,
    int wm2, int wn, int g, int tg,
    int (&D0)[2][4][4], int (&D1)[2][4][4])
{
    const uint64_t* m64 = (const uint64_t*)(sm + msk_off);
    const int p32 = p * 32;
#pragma unroll
    for (int ch = 0; ch < 4; ch++) {
        uint32_t afr[2][4];
#pragma unroll
        for (int mi = 0; mi < 2; mi++) {
            int base = (wm2 * 2 + mi) * kpu64 + p32 + ch * 8 + tg;
            uint64_t mv0 = m64[base];
            uint64_t mv1 = m64[base + 4];
            uint32_t lo0 = (uint32_t)mv0, hi0 = (uint32_t)(mv0 >> 32);
            uint32_t lo1 = (uint32_t)mv1, hi1 = (uint32_t)(mv1 >> 32);
            afr[mi][0] = ((lo0 >> g) & 0x00010001u) | (((hi0 >> g) & 0x00010001u) << 8);
            afr[mi][1] = ((lo0 >> (g + 8)) & 0x00010001u) | (((hi0 >> (g + 8)) & 0x00010001u) << 8);
            afr[mi][2] = ((lo1 >> g) & 0x00010001u) | (((hi1 >> g) & 0x00010001u) << 8);
            afr[mi][3] = ((lo1 >> (g + 8)) & 0x00010001u) | (((hi1 >> (g + 8)) & 0x00010001u) << 8);
        }
        const int c0 = ((2 * ch) ^ g) << 4;
        const int c1 = ((2 * ch + 1) ^ g) << 4;
#pragma unroll
        for (int ni = 0; ni < 4; ni++) {
            const char* bb = bbase + (wn * 32 + ni * 8 + g) * 128 + tg * 4;
            uint32_t b00 = *(const uint32_t*)(bb + c0);
            uint32_t b01 = *(const uint32_t*)(bb + c1);
            mma8(D0[0][ni], afr[0], b00, b01);
            mma8(D0[1][ni], afr[1], b00, b01);
            uint32_t b10 = *(const uint32_t*)(bb + 8192 + c0);
            uint32_t b11 = *(const uint32_t*)(bb + 8192 + c1);
            mma8(D1[0][ni], afr[0], b10, b11);
            mma8(D1[1][ni], afr[1], b10, b11);
        }
    }
}

// combine: E = 254*D0 + D1 (exact int), cs = (s0/254)*float(E)
__device__ __forceinline__ void combine_all(
    float* cs, const float* S, int NOUT, int n0,
    int wm2, int wn, int g, int tg,
    int (&D0)[2][4][4], int (&D1)[2][4][4])
{
#pragma unroll
    for (int mi = 0; mi < 2; mi++)
#pragma unroll
        for (int ni = 0; ni < 4; ni++)
#pragma unroll
            for (int rh = 0; rh < 2; rh++) {
                int row = wm2 * 32 + mi * 16 + g + rh * 8;
                int col = wn * 32 + ni * 8 + tg * 2;
                int jg0 = n0 + col;
                float sc0 = __ldg(S + (jg0 < NOUT ? jg0 : 0)) * (1.0f / 254.0f);
                float sc1 = __ldg(S + (jg0 + 1 < NOUT ? jg0 + 1 : 0)) * (1.0f / 254.0f);
                int E0 = D0[mi][ni][rh * 2] * 254 + D1[mi][ni][rh * 2];
                int E1 = D0[mi][ni][rh * 2 + 1] * 254 + D1[mi][ni][rh * 2 + 1];
                *(float2*)(cs + row * 68 + col) =
                    make_float2(sc0 * (float)E0, sc1 * (float)E1);
            }
}

// scan: warp = one bl; thread = cols (2j, 2j+1) -> LDS.64 per step
template <bool IS_LAST>
__device__ __forceinline__ void scan_all(
    char* sm, const float* cs, const float* bias, int NOUT, int n0,
    int tid, int msk_out_off, float* Out, int b0)
{
    const int jj = (tid & 31) * 2;
    const int bl = tid >> 5;
    const int j0 = n0 + jj;
    float bj0 = __ldg(bias + (j0 < NOUT ? j0 : 0));
    float bj1 = __ldg(bias + (j0 + 1 < NOUT ? j0 + 1 : 0));
    const float* base = cs + bl * 16 * 68 + jj;
    float v0 = 0.0f, v1 = 0.0f;
    uint32_t mk0 = 0, mk1 = 0;
    bool f0 = false, f1 = false;
#pragma unroll
    for (int t = 0; t < 16; t++) {
        float2 c = *(const float2*)(base + t * 68);
        v0 = (v0 + c.x) + bj0;
        f0 |= (fabsf(v0 - 1.0f) < EPS);
        if (v0 >= 1.0f) { mk0 |= (1u << t); v0 -= 1.0f; }
        v1 = (v1 + c.y) + bj1;
        f1 |= (fabsf(v1 - 1.0f) < EPS);
        if (v1 >= 1.0f) { mk1 |= (1u << t); v1 -= 1.0f; }
    }
    if (j0 < NOUT) {
        if (IS_LAST)
            Out[(size_t)(b0 + bl) * NOUT + j0] = (float)__popc(mk0) * 0.0625f;
        else
            ((uint16_t*)(sm + msk_out_off))[bl * 128 + PERM4(j0)] = (uint16_t)mk0;
        if (f0) {
            int s = atomicAdd((int*)(sm + OFF_FC), 1);
            if (s < FCAPS) ((uint32_t*)(sm + OFF_FL))[s] =
                ((uint32_t)bl << 16) | (uint32_t)j0;
        }
    }
    if (j0 + 1 < NOUT) {
        if (IS_LAST)
            Out[(size_t)(b0 + bl) * NOUT + j0 + 1] = (float)__popc(mk1) * 0.0625f;
        else
            ((uint16_t*)(sm + msk_out_off))[bl * 128 + PERM4(j0 + 1)] = (uint16_t)mk1;
        if (f1) {
            int s = atomicAdd((int*)(sm + OFF_FC), 1);
            if (s < FCAPS) ((uint32_t*)(sm + OFF_FL))[s] =
                ((uint32_t)bl << 16) | (uint32_t)(j0 + 1);
        }
    }
}

__device__ __forceinline__ uint32_t repair_scan(float acc, float bj, int lane) {
    float v = 0.0f;
    uint32_t msk = 0;
#pragma unroll
    for (int t = 0; t < TSTEPS; t++) {
        float a = __shfl_sync(0xFFFFFFFFu, acc, (lane & 16) + t);
        v = (v + a) + bj;
        if (v >= 1.0f) { msk |= (1u << t); v -= 1.0f; }
    }
    return msk;
}

// ---------------- K=128 layer: NT tiles, double-buffered B ----------------
template <int NT, int NOUT, bool IS_LAST>
__device__ void layer_k128(char* sm, uint32_t sbase, int msk_in_off,
                           const int8_t* Q, const float* S, const float* bias,
                           int msk_out_off, float* Out, int b0,
                           int tid, int wm2, int wn, int g, int tg)
{
    auto loadB = [&](int nt) {
        const int n0t = nt * 64, buf = nt & 1;
        for (int v = tid; v < 1024; v += 256) {
            int l = v >> 9, rem = v & 511, r = rem >> 3, c8 = rem & 7;
            int row = n0t + r;
            uint32_t ssz = (row < NOUT) ? 16u : 0u;
            int rc = row < NOUT ? row : 0;
            cpa16(sbase + OFF_BB + buf * 16384 + l * 8192 + r * 128 + ((c8 ^ (r & 7)) << 4),
                  Q + ((size_t)l * NOUT + rc) * 128 + c8 * 16, ssz);
        }
        asm volatile("cp.async.commit_group;");
    };
    loadB(0);
    loadB(1);                               // NT >= 2 always here
    asm volatile("cp.async.wait_group 1;"); // B(0) ready
    __syncthreads();

    float* cs = (float*)(sm + OFF_M0);      // overlays dead M0 region
#pragma unroll 1
    for (int nt = 0; nt < NT; nt++) {
        const int n0 = nt * 64, buf = nt & 1;
        int D0[2][4][4], D1[2][4][4];
#pragma unroll
        for (int mi = 0; mi < 2; mi++)
#pragma unroll
            for (int ni = 0; ni < 4; ni++)
#pragma unroll
                for (int r = 0; r < 4; r++) { D0[mi][ni][r] = 0; D1[mi][ni][r] = 0; }

        mma_panel_reg(sm, msk_in_off, 32, 0,
                      sm + OFF_BB + buf * 16384, wm2, wn, g, tg, D0, D1);
        combine_all(cs, S, NOUT, n0, wm2, wn, g, tg, D0, D1);
        __syncthreads();                    // cs readable; B(buf) free
        if (nt + 2 < NT) loadB(nt + 2);     // refill just-freed buf
        scan_all<IS_LAST>(sm, cs, bias, NOUT, n0, tid, msk_out_off, Out, b0);
        if (nt + 2 < NT)      asm volatile("cp.async.wait_group 1;");  // B(nt+1) done
        else if (nt + 1 < NT) asm volatile("cp.async.wait_group 0;");
        __syncthreads();                    // scan done + next B ready
    }
}

// ---------------- K=128 repair (masks permuted; ascending-i order) --------
template <bool IS_LAST>
__device__ void repair_k128(char* sm, int msk_prev_off, const float* W,
                            const float* bias, int msk_fix_off, float* Out,
                            int NOUT, int b0, int tid, int lane, int wid)
{
    int n = *(int*)(sm + OFF_FC);
    if (n > FCAPS) n = FCAPS;
    const uint16_t* mp = (const uint16_t*)(sm + msk_prev_off);
    for (int f0 = wid * 2; f0 < n; f0 += 16) {
        int s = f0 + (lane >> 4), tl = lane & 15;
        float acc = 0.0f;
        int bl = 0, j = 0;
        bool act = (s < n);
        if (act) {
            uint32_t pk = ((uint32_t*)(sm + OFF_FL))[s];
            bl = (int)(pk >> 16); j = (int)(pk & 0xFFFFu);
            const float* wr = W + (size_t)j * 128;
            const uint32_t bit = 1u << tl;
            const uint16_t* mr = mp + bl * 128;
            for (int i4 = 0; i4 < 128; i4 += 4) {   // logical ascending order
                if (mr[i4 + 0] & bit) acc += wr[i4 + 0];
                if (mr[i4 + 2] & bit) acc += wr[i4 + 1];
                if (mr[i4 + 1] & bit) acc += wr[i4 + 2];
                if (mr[i4 + 3] & bit) acc += wr[i4 + 3];
            }
        }
        float bj = act ? __ldg(bias + j) : 0.0f;
        uint32_t msk = repair_scan(acc, bj, lane);
        if (act && (lane & 15) == 0) {
            if (IS_LAST)
                Out[(size_t)(b0 + bl) * NOUT + j] = (float)__popc(msk) * 0.0625f;
            else
                ((uint16_t*)(sm + msk_fix_off))[bl * 128 + PERM4(j)] = (uint16_t)msk;
        }
    }
    __syncthreads();
    if (tid == 0) *(int*)(sm + OFF_FC) = 0;
    __syncthreads();
}

// ---------------- the fused kernel ----------------
__global__ void __launch_bounds__(256, 3) fused_spike(
    const float* __restrict__ F,
    const float* __restrict__ W1, const float* __restrict__ b1,
    const float* __restrict__ W2, const float* __restrict__ b2,
    const float* __restrict__ W3, const float* __restrict__ b3,
    const float* __restrict__ W4, const float* __restrict__ b4,
    float* __restrict__ Out)
{
    extern __shared__ __align__(16) char sm[];
    const uint32_t sbase = smem_u32(sm);
    const int tid = threadIdx.x;
    const int lane = tid & 31, wid = tid >> 5;
    const int wm2 = wid >> 1, wn = wid & 1;
    const int g = lane >> 2, tg = lane & 3;
    const int b0 = blockIdx.x * 8;

    // ---- encoder (bit-exact), written directly permuted into M0 ----
    {
        uint16_t* m0 = (uint16_t*)(sm + OFF_M0);
#pragma unroll 1
        for (int bl = 0; bl < 8; bl++) {
            const float* fr = F + (size_t)(b0 + bl) * 784;
            for (int i = tid; i < KP1; i += 256) {
                unsigned m = 0;
                if (i < 784) {
                    float x = fr[i], v = 0.0f;
#pragma unroll
                    for (int t = 0; t < TSTEPS; t++) {
                        v += x;
                        if (v >= 1.0f) { m |= (1u << t); v -= 1.0f; }
                    }
                }
                m0[bl * KP1 + PERM4(i)] = (uint16_t)m;
            }
        }
        if (tid == 0) *(int*)(sm + OFF_FC) = 0;
        __syncthreads();
    }

    // ---- layer 1: K=896, 2 N-tiles, double-buffered K panels ----
#pragma unroll 1
    for (int nt = 0; nt < 2; nt++) {
        const int n0 = nt * 64;
        int D0[2][4][4], D1[2][4][4];
#pragma unroll
        for (int mi = 0; mi < 2; mi++)
#pragma unroll
            for (int ni = 0; ni < 4; ni++)
#pragma unroll
                for (int r = 0; r < 4; r++) { D0[mi][ni][r] = 0; D1[mi][ni][r] = 0; }

        auto loadB1 = [&](int p, int buf) {
            for (int v = tid; v < 1024; v += 256) {
                int l = v >> 9, rem = v & 511, r = rem >> 3, c8 = rem & 7;
                cpa16(sbase + OFF_BB + buf * 16384 + l * 8192 + r * 128 + ((c8 ^ (r & 7)) << 4),
                      g_Q1 + ((size_t)l * 128 + n0 + r) * KP1 + p * 128 + c8 * 16, 16u);
            }
            asm volatile("cp.async.commit_group;");
        };
        loadB1(0, 0);
        asm volatile("cp.async.wait_group 0;");
        __syncthreads();
#pragma unroll 1
        for (int p = 0; p < 7; p++) {
            const int buf = p & 1;
            if (p < 6) loadB1(p + 1, buf ^ 1);
            mma_panel_reg(sm, OFF_M0, KP1 / 4, p, sm + OFF_BB + buf * 16384,
                          wm2, wn, g, tg, D0, D1);
            if (p < 6) asm volatile("cp.async.wait_group 0;");
            __syncthreads();                 // mma(buf) done by all + B(p+1) ready
        }
        // epilogue: cs overlays both (now free) B bufs
        float* cs = (float*)(sm + OFF_BB);
        combine_all(cs, g_S1, 128, n0, wm2, wn, g, tg, D0, D1);
        __syncthreads();
        scan_all<false>(sm, cs, b1, 128, n0, tid, OFF_M1, nullptr, b0);
        __syncthreads();
    }
    // ---- layer 1 repair (permuted M0, K=784, gmem W1) ----
    {
        int n = *(int*)(sm + OFF_FC);
        if (n > FCAPS) n = FCAPS;
        const uint16_t* mp = (const uint16_t*)(sm + OFF_M0);
        for (int f0 = wid * 2; f0 < n; f0 += 16) {
            int s = f0 + (lane >> 4), tl = lane & 15;
            float acc = 0.0f;
            int bl = 0, j = 0;
            bool act = (s < n);
            if (act) {
                uint32_t pk = ((uint32_t*)(sm + OFF_FL))[s];
                bl = (int)(pk >> 16); j = (int)(pk & 0xFFFFu);
                const float* wr = W1 + (size_t)j * 784;
                const uint32_t bit = 1u << tl;
                const uint16_t* mr = mp + bl * KP1;
                for (int i4 = 0; i4 < 784; i4 += 4) {
                    if (mr[i4 + 0] & bit) acc += wr[i4 + 0];
                    if (mr[i4 + 2] & bit) acc += wr[i4 + 1];
                    if (mr[i4 + 1] & bit) acc += wr[i4 + 2];
                    if (mr[i4 + 3] & bit) acc += wr[i4 + 3];
                }
            }
            float bj = act ? __ldg(b1 + j) : 0.0f;
            uint32_t msk = repair_scan(acc, bj, lane);
            if (act && (lane & 15) == 0)
                ((uint16_t*)(sm + OFF_M1))[bl * 128 + PERM4(j)] = (uint16_t)msk;
        }
        __syncthreads();
        if (tid == 0) *(int*)(sm + OFF_FC) = 0;
        __syncthreads();
    }

    // ---- layers 2,3 + repairs (cs overlays dead M0; M3 aliases M1) ----
    layer_k128<2, 128, false>(sm, sbase, OFF_M1, g_Q2, g_S2, b2,
                              OFF_M2, nullptr, b0, tid, wm2, wn, g, tg);
    repair_k128<false>(sm, OFF_M1, W2, b2, OFF_M2, nullptr, 128,
                       b0, tid, lane, wid);

    layer_k128<2, 128, false>(sm, sbase, OFF_M2, g_Q3, g_S3, b3,
                              OFF_M1, nullptr, b0, tid, wm2, wn, g, tg);
    repair_k128<false>(sm, OFF_M2, W3, b3, OFF_M1, nullptr, 128,
                       b0, tid, lane, wid);

    // ---- layer 4 + repair ----
    layer_k128<13, 784, true>(sm, sbase, OFF_M1, g_Q4, g_S4, b4,
                              0, Out, b0, tid, wm2, wn, g, tg);
    repair_k128<true>(sm, OFF_M1, W4, b4, 0, Out, 784, b0, tid, lane, wid);
}

// ---------------------------------------------------------------------------
extern "C" void kernel_launch(void* const* d_in, const int* in_sizes, int n_in,
                              void* d_out, int out_size)
{
    const float* features = (const float*)d_in[0];
    const float* W1 = (const float*)d_in[1];
    const float* b1 = (const float*)d_in[2];
    const float* W2 = (const float*)d_in[3];
    const float* b2 = (const float*)d_in[4];
    const float* W3 = (const float*)d_in[5];
    const float* b3 = (const float*)d_in[6];
    const float* W4 = (const float*)d_in[7];
    const float* b4 = (const float*)d_in[8];
    float* out = (float*)d_out;

    cudaFuncSetAttribute(fused_spike,
                         cudaFuncAttributeMaxDynamicSharedMemorySize, SMEMSZ);

    wsplit_all<<<1168, 32>>>(W1, W2, W3, W4);
    fused_spike<<<BATCH / 8, 256, SMEMSZ>>>(features, W1, b1, W2, b2,
                                            W3, b3, W4, b4, out);
}

// round 16
// speedup vs baseline: 1.1249x; 1.1249x over previous
#include <cuda_runtime.h>
#include <stdint.h>

// AE_spikes: separate kernels per layer (R9 architecture, measured faster
// than fused) with R12-validated internals: register-built A fragments from
// PERMUTED bitmasks (no A smem panel), 2 s8 weight limbs base 254 with
// E-trick combine (E=254*D0+D1, one I2F), fused fire-and-reset scan with
// near-threshold flagging, and bit-exact t-parallel warp repair.

#define BATCH  16384
#define TSTEPS 16
#define KP1    896
#define EPS    1e-3f
#define FCAP   1048576

// logical neuron index -> permuted u16 slot (pairs (0,2),(1,3) per u64)
#define PERM4(i) (((i) & ~3) | ((((i) & 1) << 1) | (((i) >> 1) & 1)))

// ---------------- scratch ----------------
__device__ uint16_t g_M0[BATCH * KP1];     // permuted
__device__ uint16_t g_M1[BATCH * 128];     // permuted
__device__ uint16_t g_M2[BATCH * 128];
__device__ uint16_t g_M3[BATCH * 128];
__device__ int8_t   g_Q1[2 * 128 * KP1];
__device__ int8_t   g_Q2[2 * 128 * 128];
__device__ int8_t   g_Q3[2 * 128 * 128];
__device__ int8_t   g_Q4[2 * 784 * 128];
__device__ float    g_S1[128], g_S2[128], g_S3[128], g_S4[784];
__device__ int      g_cnt[4];
__device__ uint32_t g_flag[4][FCAP];

// ---------------- helpers ----------------
__device__ __forceinline__ uint32_t smem_u32(const void* p) {
    uint32_t a;
    asm("{ .reg .u64 t; cvta.to.shared.u64 t, %1; cvt.u32.u64 %0, t; }"
        : "=r"(a) : "l"(p));
    return a;
}
__device__ __forceinline__ void mma8(int* d, const uint32_t* a, uint32_t b0, uint32_t b1) {
    asm volatile(
        "mma.sync.aligned.m16n8k32.row.col.s32.s8.s8.s32 "
        "{%0,%1,%2,%3}, {%4,%5,%6,%7}, {%8,%9}, {%0,%1,%2,%3};"
        : "+r"(d[0]), "+r"(d[1]), "+r"(d[2]), "+r"(d[3])
        : "r"(a[0]), "r"(a[1]), "r"(a[2]), "r"(a[3]), "r"(b0), "r"(b1));
}
__device__ __forceinline__ void cpa16(uint32_t dst, const void* src, uint32_t ssz) {
    asm volatile("cp.async.cg.shared.global [%0], [%1], 16, %2;"
                 :: "r"(dst), "l"(src), "r"(ssz));
}

__global__ void zero_cnt_kernel() { if (threadIdx.x < 4) g_cnt[threadIdx.x] = 0; }

// ---------------- encoder: bit-exact, writes PERMUTED masks ----------------
__global__ void __launch_bounds__(256) enc_kernel(const float* __restrict__ f) {
    int idx = blockIdx.x * blockDim.x + threadIdx.x;
    if (idx >= BATCH * KP1) return;
    int b = idx / KP1, i = idx - b * KP1;
    unsigned m = 0;
    if (i < 784) {
        float x = f[b * 784 + i], v = 0.0f;
#pragma unroll
        for (int t = 0; t < TSTEPS; t++) {
            v += x;
            if (v >= 1.0f) { m |= (1u << t); v -= 1.0f; }
        }
    }
    g_M0[(size_t)b * KP1 + PERM4(i)] = (uint16_t)m;
}

// ---------------- weight split (one launch) ----------------
__device__ void wsplit_one(const float* W, int8_t* Q, float* S,
                           int N, int K, int KP, int j, int lane) {
    const float* w = W + (size_t)j * K;
    float m = 0.0f;
    for (int k = lane; k < K; k += 32) m = fmaxf(m, fabsf(w[k]));
#pragma unroll
    for (int o = 16; o; o >>= 1) m = fmaxf(m, __shfl_xor_sync(~0u, m, o));
    float s0 = (m > 0.0f) ? m / 127.0f : 1.0f;
    if (lane == 0) S[j] = s0;
    double s0d = (double)s0;
    for (int k = lane; k < KP; k += 32) {
        double q0 = 0.0, q1 = 0.0;
        if (k < K) {
            double wd = (double)w[k];
            q0 = fmin(fmax(rint(wd / s0d), -127.0), 127.0);
            double r1 = wd - q0 * s0d;
            q1 = fmin(fmax(rint(r1 * 254.0 / s0d), -127.0), 127.0);
        }
        size_t base = (size_t)j * KP + k, lstr = (size_t)N * KP;
        Q[base]        = (int8_t)(int)q0;
        Q[base + lstr] = (int8_t)(int)q1;
    }
}
__global__ void __launch_bounds__(32) wsplit_all(
    const float* __restrict__ W1, const float* __restrict__ W2,
    const float* __restrict__ W3, const float* __restrict__ W4)
{
    int bid = blockIdx.x, lane = threadIdx.x;
    if      (bid < 128) wsplit_one(W1, g_Q1, g_S1, 128, 784, KP1, bid, lane);
    else if (bid < 256) wsplit_one(W2, g_Q2, g_S2, 128, 128, 128, bid - 128, lane);
    else if (bid < 384) wsplit_one(W3, g_Q3, g_S3, 128, 128, 128, bid - 256, lane);
    else                wsplit_one(W4, g_Q4, g_S4, 784, 128, 128, bid - 384, lane);
}

// ---------------- register A-expansion + MMA over one K=128 panel ---------
// Masks permuted per u64: lo=(m0|m2<<16), hi=(m1|m3<<16). B pitch 144.
__device__ __forceinline__ void mma_panel_reg(
    const char* sm, int msk_off, int kpu64, int p, const char* bbase,
    int wm2, int wn, int g, int tg,
    int (&D0)[2][4][4], int (&D1)[2][4][4])
{
    const uint64_t* m64 = (const uint64_t*)(sm + msk_off);
    const int p32 = p * 32;
#pragma unroll
    for (int ch = 0; ch < 4; ch++) {
        uint32_t afr[2][4];
#pragma unroll
        for (int mi = 0; mi < 2; mi++) {
            int base = (wm2 * 2 + mi) * kpu64 + p32 + ch * 8 + tg;
            uint64_t mv0 = m64[base];
            uint64_t mv1 = m64[base + 4];
            uint32_t lo0 = (uint32_t)mv0, hi0 = (uint32_t)(mv0 >> 32);
            uint32_t lo1 = (uint32_t)mv1, hi1 = (uint32_t)(mv1 >> 32);
            afr[mi][0] = ((lo0 >> g) & 0x00010001u) | (((hi0 >> g) & 0x00010001u) << 8);
            afr[mi][1] = ((lo0 >> (g + 8)) & 0x00010001u) | (((hi0 >> (g + 8)) & 0x00010001u) << 8);
            afr[mi][2] = ((lo1 >> g) & 0x00010001u) | (((hi1 >> g) & 0x00010001u) << 8);
            afr[mi][3] = ((lo1 >> (g + 8)) & 0x00010001u) | (((hi1 >> (g + 8)) & 0x00010001u) << 8);
        }
#pragma unroll
        for (int ni = 0; ni < 4; ni++) {
            const char* bb = bbase + (wn * 32 + ni * 8 + g) * 144 + ch * 32;
            uint32_t b00 = *(const uint32_t*)(bb + tg * 4);
            uint32_t b01 = *(const uint32_t*)(bb + 16 + tg * 4);
            mma8(D0[0][ni], afr[0], b00, b01);
            mma8(D0[1][ni], afr[1], b00, b01);
            uint32_t b10 = *(const uint32_t*)(bb + 9216 + tg * 4);
            uint32_t b11 = *(const uint32_t*)(bb + 9216 + 16 + tg * 4);
            mma8(D1[0][ni], afr[0], b10, b11);
            mma8(D1[1][ni], afr[1], b10, b11);
        }
    }
}

// combine: E = 254*D0 + D1 (exact int), cs = (s0/254)*float(E)
__device__ __forceinline__ void combine_all(
    float* cs, const float* S, int NOUT, int n0,
    int wm2, int wn, int g, int tg,
    int (&D0)[2][4][4], int (&D1)[2][4][4])
{
#pragma unroll
    for (int mi = 0; mi < 2; mi++)
#pragma unroll
        for (int ni = 0; ni < 4; ni++)
#pragma unroll
            for (int rh = 0; rh < 2; rh++) {
                int row = wm2 * 32 + mi * 16 + g + rh * 8;
                int col = wn * 32 + ni * 8 + tg * 2;
                int jg0 = n0 + col;
                float sc0 = __ldg(S + (jg0 < NOUT ? jg0 : 0)) * (1.0f / 254.0f);
                float sc1 = __ldg(S + (jg0 + 1 < NOUT ? jg0 + 1 : 0)) * (1.0f / 254.0f);
                int E0 = D0[mi][ni][rh * 2] * 254 + D1[mi][ni][rh * 2];
                int E1 = D0[mi][ni][rh * 2 + 1] * 254 + D1[mi][ni][rh * 2 + 1];
                *(float2*)(cs + row * 68 + col) =
                    make_float2(sc0 * (float)E0, sc1 * (float)E1);
            }
}

// scan: 512 chains, 2 per thread (R9-proven form); permuted mask writes
template <bool IS_LAST, int LID>
__device__ __forceinline__ void scan_all(
    const float* cs, const float* bias, int NOUT, int n0, int tid,
    uint16_t* Mout, float* Out, int b0)
{
#pragma unroll
    for (int u = 0; u < 2; u++) {
        int pr = tid + 256 * u;
        int j = pr & 63, bl = pr >> 6;
        int jj = n0 + j;
        if (jj < NOUT) {
            float bj = __ldg(bias + jj);
            const float* colp = cs + bl * 16 * 68 + j;
            float v = 0.0f;
            uint32_t msk = 0;
            bool flag = false;
#pragma unroll
            for (int t = 0; t < 16; t++) {
                v = (v + colp[t * 68]) + bj;
                flag |= (fabsf(v - 1.0f) < EPS);
                if (v >= 1.0f) { msk |= (1u << t); v -= 1.0f; }
            }
            int b = b0 + bl;
            if (IS_LAST)
                Out[(size_t)b * NOUT + jj] = (float)__popc(msk) * 0.0625f;
            else
                Mout[(size_t)b * 128 + PERM4(jj)] = (uint16_t)msk;
            if (flag) {
                int s = atomicAdd(&g_cnt[LID], 1);
                if (s < FCAP) g_flag[LID][s] = ((uint32_t)b << 10) | (uint32_t)jj;
            }
        }
    }
}

// ---------------- layer 1 kernel: K=896, NOUT=128, 2 N-tiles --------------
// smem: masks 14336 | B 2x18432 (cs overlays B) = 51200
__global__ void __launch_bounds__(256, 3) gemm_L1(
    const uint16_t* __restrict__ Min, const float* __restrict__ bias,
    uint16_t* __restrict__ Mout)
{
    extern __shared__ __align__(16) char sm[];
    const uint32_t sbase = smem_u32(sm);
    constexpr int OFF_B = 14336;
    const int tid = threadIdx.x;
    const int lane = tid & 31, wid = tid >> 5;
    const int wm2 = wid >> 1, wn = wid & 1;
    const int g = lane >> 2, tg = lane & 3;
    const int b0 = blockIdx.x * 8;

    {   // stage permuted masks (straight copy)
        const uint4* msrc = (const uint4*)(Min + (size_t)b0 * KP1);
        uint4* mdst = (uint4*)sm;
        for (int u = tid; u < 896; u += 256) mdst[u] = msrc[u];
    }
    __syncthreads();

#pragma unroll 1
    for (int nt = 0; nt < 2; nt++) {
        const int n0 = nt * 64;
        int D0[2][4][4], D1[2][4][4];
#pragma unroll
        for (int mi = 0; mi < 2; mi++)
#pragma unroll
            for (int ni = 0; ni < 4; ni++)
#pragma unroll
                for (int r = 0; r < 4; r++) { D0[mi][ni][r] = 0; D1[mi][ni][r] = 0; }

        auto loadB1 = [&](int p, int buf) {
            for (int v = tid; v < 1024; v += 256) {
                int l = v >> 9, rem = v & 511, r = rem >> 3, c8 = rem & 7;
                cpa16(sbase + OFF_B + buf * 18432 + l * 9216 + r * 144 + c8 * 16,
                      g_Q1 + ((size_t)l * 128 + n0 + r) * KP1 + p * 128 + c8 * 16, 16u);
            }
            asm volatile("cp.async.commit_group;");
        };
        loadB1(0, 0);
        asm volatile("cp.async.wait_group 0;");
        __syncthreads();
#pragma unroll 1
        for (int p = 0; p < 7; p++) {
            const int buf = p & 1;
            if (p < 6) loadB1(p + 1, buf ^ 1);
            mma_panel_reg(sm, 0, KP1 / 4, p, sm + OFF_B + buf * 18432,
                          wm2, wn, g, tg, D0, D1);
            if (p < 6) asm volatile("cp.async.wait_group 0;");
            __syncthreads();
        }
        float* cs = (float*)(sm + OFF_B);    // both B bufs free now
        combine_all(cs, g_S1, 128, n0, wm2, wn, g, tg, D0, D1);
        __syncthreads();
        scan_all<false, 0>(cs, bias, 128, n0, tid, Mout, nullptr, b0);
        __syncthreads();
    }
}

// ---------------- K=128 layer kernel: NT tiles in-CTA ---------------------
// smem: masks 2048 | B0 18432 | cs 34816 = 55296
template <int NT, int NOUT, bool IS_LAST, int LID>
__global__ void __launch_bounds__(256, 3) gemm_K128(
    const uint16_t* __restrict__ Min, const int8_t* __restrict__ Q,
    const float* __restrict__ S, const float* __restrict__ bias,
    uint16_t* __restrict__ Mout, float* __restrict__ Out)
{
    extern __shared__ __align__(16) char sm[];
    const uint32_t sbase = smem_u32(sm);
    constexpr int OFF_B = 2048, OFF_CS = 20480;
    const int tid = threadIdx.x;
    const int lane = tid & 31, wid = tid >> 5;
    const int wm2 = wid >> 1, wn = wid & 1;
    const int g = lane >> 2, tg = lane & 3;
    const int b0 = blockIdx.x * 8;

    {   // stage permuted masks
        const uint4* msrc = (const uint4*)(Min + (size_t)b0 * 128);
        uint4* mdst = (uint4*)sm;
        for (int u = tid; u < 128; u += 256) mdst[u] = msrc[u];
    }
    auto loadB = [&](int nt) {
        const int n0t = nt * 64;
        for (int v = tid; v < 1024; v += 256) {
            int l = v >> 9, rem = v & 511, r = rem >> 3, c8 = rem & 7;
            int row = n0t + r;
            uint32_t ssz = (row < NOUT) ? 16u : 0u;
            int rc = row < NOUT ? row : 0;
            cpa16(sbase + OFF_B + l * 9216 + r * 144 + c8 * 16,
                  Q + ((size_t)l * NOUT + rc) * 128 + c8 * 16, ssz);
        }
        asm volatile("cp.async.commit_group;");
    };
    loadB(0);
    asm volatile("cp.async.wait_group 0;");
    __syncthreads();

    float* cs = (float*)(sm + OFF_CS);
#pragma unroll 1
    for (int nt = 0; nt < NT; nt++) {
        const int n0 = nt * 64;
        int D0[2][4][4], D1[2][4][4];
#pragma unroll
        for (int mi = 0; mi < 2; mi++)
#pragma unroll
            for (int ni = 0; ni < 4; ni++)
#pragma unroll
                for (int r = 0; r < 4; r++) { D0[mi][ni][r] = 0; D1[mi][ni][r] = 0; }

        mma_panel_reg(sm, 0, 32, 0, sm + OFF_B, wm2, wn, g, tg, D0, D1);
        combine_all(cs, S, NOUT, n0, wm2, wn, g, tg, D0, D1);
        __syncthreads();                     // B free, cs readable
        if (nt + 1 < NT) loadB(nt + 1);      // overlaps scan
        scan_all<IS_LAST, LID>(cs, bias, NOUT, n0, tid, Mout, Out, b0);
        if (nt + 1 < NT) asm volatile("cp.async.wait_group 0;");
        __syncthreads();
    }
}

// ---------------- repair: t-parallel warp, permuted-mask reads ------------
__device__ __forceinline__ uint32_t repair_scan(float acc, float bj, int lane) {
    float v = 0.0f;
    uint32_t msk = 0;
#pragma unroll
    for (int t = 0; t < TSTEPS; t++) {
        float a = __shfl_sync(0xFFFFFFFFu, acc, (lane & 16) + t);
        v = (v + a) + bj;
        if (v >= 1.0f) { msk |= (1u << t); v -= 1.0f; }
    }
    return msk;
}

template <int KP, int K, int NOUT, bool IS_LAST, int LID>
__global__ void __launch_bounds__(256) repair_kernel(
    const uint16_t* __restrict__ Min, const float* __restrict__ W,
    const float* __restrict__ bias, uint16_t* __restrict__ Mout,
    float* __restrict__ Out)
{
    int n = g_cnt[LID];
    if (n > FCAP) n = FCAP;
    const int lane = threadIdx.x & 31;
    const int grp = lane >> 4, tl = lane & 15;
    const int wglob = (blockIdx.x * blockDim.x + threadIdx.x) >> 5;
    const int nwarps = (gridDim.x * blockDim.x) >> 5;

    for (int s0 = wglob * 2; s0 < n; s0 += nwarps * 2) {
        int s = s0 + grp;
        float acc = 0.0f;
        int b = 0, j = 0;
        bool act = (s < n);
        if (act) {
            uint32_t pk = g_flag[LID][s];
            b = (int)(pk >> 10); j = (int)(pk & 1023u);
            const uint16_t* mr = Min + (size_t)b * KP;
            const float* wr = W + (size_t)j * K;
            const uint32_t bit = 1u << tl;
            for (int i4 = 0; i4 < K; i4 += 4) {   // logical ascending order
                if (mr[i4 + 0] & bit) acc += wr[i4 + 0];
                if (mr[i4 + 2] & bit) acc += wr[i4 + 1];
                if (mr[i4 + 1] & bit) acc += wr[i4 + 2];
                if (mr[i4 + 3] & bit) acc += wr[i4 + 3];
            }
        }
        float bj = act ? __ldg(bias + j) : 0.0f;
        uint32_t msk = repair_scan(acc, bj, lane);
        if (act && tl == 0) {
            if (IS_LAST)
                Out[(size_t)b * NOUT + j] = (float)__popc(msk) * 0.0625f;
            else
                Mout[(size_t)b * 128 + PERM4(j)] = (uint16_t)msk;
        }
    }
}

// ---------------------------------------------------------------------------
extern "C" void kernel_launch(void* const* d_in, const int* in_sizes, int n_in,
                              void* d_out, int out_size)
{
    const float* features = (const float*)d_in[0];
    const float* W1 = (const float*)d_in[1];
    const float* b1 = (const float*)d_in[2];
    const float* W2 = (const float*)d_in[3];
    const float* b2 = (const float*)d_in[4];
    const float* W3 = (const float*)d_in[5];
    const float* b3 = (const float*)d_in[6];
    const float* W4 = (const float*)d_in[7];
    const float* b4 = (const float*)d_in[8];
    float* out = (float*)d_out;

    uint16_t *m0, *m1, *m2, *m3;
    int8_t *q2, *q3, *q4;
    float *s2, *s3, *s4;
    cudaGetSymbolAddress((void**)&m0, g_M0);
    cudaGetSymbolAddress((void**)&m1, g_M1);
    cudaGetSymbolAddress((void**)&m2, g_M2);
    cudaGetSymbolAddress((void**)&m3, g_M3);
    cudaGetSymbolAddress((void**)&q2, g_Q2);
    cudaGetSymbolAddress((void**)&q3, g_Q3);
    cudaGetSymbolAddress((void**)&q4, g_Q4);
    cudaGetSymbolAddress((void**)&s2, g_S2);
    cudaGetSymbolAddress((void**)&s3, g_S3);
    cudaGetSymbolAddress((void**)&s4, g_S4);

    constexpr int SM_L1 = 14336 + 2 * 18432;           // 51200
    constexpr int SM_K  = 2048 + 18432 + 34816;        // 55296

    cudaFuncSetAttribute(gemm_L1,
                         cudaFuncAttributeMaxDynamicSharedMemorySize, SM_L1);
    cudaFuncSetAttribute(gemm_K128<2, 128, false, 1>,
                         cudaFuncAttributeMaxDynamicSharedMemorySize, SM_K);
    cudaFuncSetAttribute(gemm_K128<2, 128, false, 2>,
                         cudaFuncAttributeMaxDynamicSharedMemorySize, SM_K);
    cudaFuncSetAttribute(gemm_K128<13, 784, true, 3>,
                         cudaFuncAttributeMaxDynamicSharedMemorySize, SM_K);

    zero_cnt_kernel<<<1, 32>>>();
    enc_kernel<<<(BATCH * KP1 + 255) / 256, 256>>>(features);
    wsplit_all<<<1168, 32>>>(W1, W2, W3, W4);

    gemm_L1<<<BATCH / 8, 256, SM_L1>>>(m0, b1, m1);
    repair_kernel<KP1, 784, 128, false, 0><<<296, 256>>>(m0, W1, b1, m1, nullptr);

    gemm_K128<2, 128, false, 1><<<BATCH / 8, 256, SM_K>>>(m1, q2, s2, b2, m2, nullptr);
    repair_kernel<128, 128, 128, false, 1><<<296, 256>>>(m1, W2, b2, m2, nullptr);

    gemm_K128<2, 128, false, 2><<<BATCH / 8, 256, SM_K>>>(m2, q3, s3, b3, m3, nullptr);
    repair_kernel<128, 128, 128, false, 2><<<296, 256>>>(m2, W3, b3, m3, nullptr);

    gemm_K128<13, 784, true, 3><<<BATCH / 8, 256, SM_K>>>(m3, q4, s4, b4, nullptr, out);
    repair_kernel<128, 128, 784, true, 3><<<296, 256>>>(m3, W4, b4, nullptr, out);
}